// round 14
// baseline (speedup 1.0000x reference)
#include <cuda_runtime.h>
#include <cuda_fp16.h>
#include <math.h>
#include <stdint.h>
#include <string.h>

#define NROWS 8192
#define H 512
#define CC 100
#define RR 69
#define PP 69
#define EPSV 1e-8f
#define NPAIRS (CC * CC)
#define MAXR 4

typedef unsigned long long ull;

// ---------------- scratch (device globals, no runtime alloc) ----------------
__device__ __half g_vcat[(size_t)NROWS * 3 * H];
__device__ __half g_h[(size_t)NROWS * H];
__device__ float  g_vf[(size_t)NROWS * H];
__device__ __half g_rf[(size_t)NROWS * 2 * H];
__device__ float  g_h2[(size_t)NROWS * H];
__device__ __half g_w1t[(size_t)H * 3 * H];
__device__ __half g_w2t[(size_t)H * H];
__device__ __half g_rw1t[(size_t)H * 2 * H];
// dedup scratch
__device__ int g_hist[NPAIRS];
__device__ int g_offs[NPAIRS];     // mutable (scatter cursor)
__device__ int g_start[NPAIRS];    // clean exclusive offsets
__device__ int g_perm[NROWS];
__device__ int g_units[NROWS];
__device__ int g_nunits;

// ---------------- helpers ----------------
__device__ __forceinline__ uint32_t pack_h2(float a, float b) {
    __half2 h = __floats2half2_rn(a, b);
    uint32_t r; memcpy(&r, &h, 4); return r;
}
__device__ __forceinline__ uint32_t smem_u32(const void* p) {
    return (uint32_t)__cvta_generic_to_shared(p);
}
__device__ __forceinline__ void cp_async16(uint32_t smem_dst, const void* gmem_src) {
    asm volatile("cp.async.cg.shared.global [%0], [%1], 16;" :: "r"(smem_dst), "l"(gmem_src) : "memory");
}
__device__ __forceinline__ void cp_commit() {
    asm volatile("cp.async.commit_group;" ::: "memory");
}
#define CP_WAIT(n) asm volatile("cp.async.wait_group %0;" :: "n"(n) : "memory")

__device__ __forceinline__ void mma16816(float* d, const uint32_t* a, const uint32_t* b) {
    asm volatile(
        "mma.sync.aligned.m16n8k16.row.col.f32.f16.f16.f32 "
        "{%0,%1,%2,%3},{%4,%5,%6,%7},{%8,%9},{%0,%1,%2,%3};"
        : "+f"(d[0]), "+f"(d[1]), "+f"(d[2]), "+f"(d[3])
        : "r"(a[0]), "r"(a[1]), "r"(a[2]), "r"(a[3]), "r"(b[0]), "r"(b[1]));
}
__device__ __forceinline__ void ldsm4(uint32_t& r0, uint32_t& r1, uint32_t& r2, uint32_t& r3,
                                      uint32_t addr) {
    asm volatile("ldmatrix.sync.aligned.m8n8.x4.shared.b16 {%0,%1,%2,%3}, [%4];"
        : "=r"(r0), "=r"(r1), "=r"(r2), "=r"(r3) : "r"(addr));
}

// ---------------- dedup kernels ----------------
__global__ void pair_hist_kernel(const int* __restrict__ scats,
                                 const int* __restrict__ ocats) {
    int n = blockIdx.x * blockDim.x + threadIdx.x;
    if (n < NROWS) atomicAdd(&g_hist[scats[n] * CC + ocats[n]], 1);
}

__global__ __launch_bounds__(1024)
void pair_scan_kernel() {       // single block
    __shared__ int part[1024];
    const int tid = threadIdx.x;
    const int per = (NPAIRS + 1023) / 1024;    // 10
    const int base = tid * per;
    int sum = 0;
    for (int i = 0; i < per; i++) {
        int idx = base + i;
        if (idx < NPAIRS) sum += g_hist[idx];
    }
    part[tid] = sum;
    __syncthreads();
    for (int off = 1; off < 1024; off <<= 1) {
        int v = (tid >= off) ? part[tid - off] : 0;
        __syncthreads();
        part[tid] += v;
        __syncthreads();
    }
    int excl = (tid == 0) ? 0 : part[tid - 1];
    for (int i = 0; i < per; i++) {
        int idx = base + i;
        if (idx < NPAIRS) {
            int c = g_hist[idx];
            g_offs[idx] = excl;
            g_start[idx] = excl;
            excl += c;
        }
    }
}

__global__ void pair_scatter_kernel(const int* __restrict__ scats,
                                    const int* __restrict__ ocats) {
    int n = blockIdx.x * blockDim.x + threadIdx.x;
    if (n < NROWS) {
        int p = scats[n] * CC + ocats[n];
        int pos = atomicAdd(&g_offs[p], 1);
        g_perm[pos] = n;
    }
}

__global__ void pair_units_kernel() {
    int p = blockIdx.x * blockDim.x + threadIdx.x;
    if (p >= NPAIRS) return;
    int k = g_hist[p];
    if (k == 0) return;
    int nu = (k + MAXR - 1) / MAXR;
    int base = atomicAdd(&g_nunits, nu);
    for (int i = 0; i < nu; i++)
        g_units[base + i] = (p << 8) | i;
}

// ---------------- concat -> fp16 ----------------
__global__ void concat_kernel(const float* __restrict__ s,
                              const float* __restrict__ p,
                              const float* __restrict__ o) {
    size_t idx = (size_t)blockIdx.x * blockDim.x + threadIdx.x;
    size_t total = (size_t)NROWS * 3 * H / 4;
    if (idx >= total) return;
    size_t row = idx / (3 * H / 4);
    size_t col4 = idx % (3 * H / 4);
    const float4* src;
    size_t within;
    if (col4 < H / 4)            { src = (const float4*)s; within = col4; }
    else if (col4 < 2 * (H / 4)) { src = (const float4*)p; within = col4 - H / 4; }
    else                         { src = (const float4*)o; within = col4 - 2 * (H / 4); }
    float4 v = src[row * (H / 4) + within];
    uint32_t* d = (uint32_t*)(g_vcat + idx * 4);
    d[0] = pack_h2(v.x, v.y);
    d[1] = pack_h2(v.z, v.w);
}

// ---------------- weight transpose: W[K,N] f32 -> T[N,K] fp16 ----------------
__global__ void wtrans_kernel(const float* __restrict__ W,
                              __half* __restrict__ T,
                              int K, int N) {
    size_t idx = (size_t)blockIdx.x * blockDim.x + threadIdx.x;
    size_t total = (size_t)K * N;
    if (idx >= total) return;
    int n = (int)(idx / K);
    int k = (int)(idx % K);
    T[idx] = __float2half_rn(W[(size_t)k * N + n]);
}

// ---------------- fp16 single-pass mma.sync GEMM (unchanged from R12 WIN) ----------------
#define TG_LDS 72
#define TG_STAGES 3
#define TG_STAGE_ELEMS (128 * TG_LDS)
#define TG_SMEM (2 * TG_STAGES * TG_STAGE_ELEMS * 2)
#define TG_ROWB (TG_LDS * 2)

template<bool WH16, bool WF32, bool RELU>
__global__ __launch_bounds__(256, 2)
void tgemm_kernel(const __half* __restrict__ A, const __half* __restrict__ B,
                  const float* __restrict__ bias,
                  __half* __restrict__ Ch, float* __restrict__ Cf32,
                  int K, int Ntot) {
    extern __shared__ __align__(16) __half smem[];

    const int tid = threadIdx.x;
    const int wid = tid >> 5;
    const int lane = tid & 31;
    const int g = lane >> 2;
    const int t = lane & 3;
    const int wm = wid & 3;
    const int wn = wid >> 2;
    const int bm = blockIdx.y * 128;
    const int bn = blockIdx.x * 128;

    const int C = K >> 6;

    const uint32_t aoff = (uint32_t)((wm * 32 + (lane & 15)) * TG_ROWB + ((lane >> 4) * 8) * 2);
    const uint32_t boff = (uint32_t)((wn * 64 + ((lane >> 3) >> 1) * 8 + (lane & 7)) * TG_ROWB
                                     + (((lane >> 3) & 1) * 8) * 2);

    float acc[2][8][4];
#pragma unroll
    for (int i = 0; i < 2; i++)
#pragma unroll
        for (int j = 0; j < 8; j++)
#pragma unroll
            for (int q = 0; q < 4; q++) acc[i][j][q] = 0.f;

    auto load_chunk = [&](int c, int s) {
        int kc = c << 6;
        uint32_t abase = smem_u32(smem + s * TG_STAGE_ELEMS);
        uint32_t bbase = smem_u32(smem + (TG_STAGES + s) * TG_STAGE_ELEMS);
#pragma unroll
        for (int i = 0; i < 4; i++) {
            int seg = tid + i * 256;
            int row = seg >> 3, sg = seg & 7;
            cp_async16(abase + (row * TG_LDS + sg * 8) * 2,
                       A + (size_t)(bm + row) * K + kc + sg * 8);
        }
#pragma unroll
        for (int i = 0; i < 4; i++) {
            int seg = tid + i * 256;
            int row = seg >> 3, sg = seg & 7;
            cp_async16(bbase + (row * TG_LDS + sg * 8) * 2,
                       B + (size_t)(bn + row) * K + kc + sg * 8);
        }
        cp_commit();
    };

    load_chunk(0, 0);
    load_chunk(1, 1);
    load_chunk(2, 2);

    for (int c = 0; c < C; c++) {
        const int s = c % TG_STAGES;
        CP_WAIT(2);
        __syncthreads();

        const uint32_t abase = smem_u32(smem + s * TG_STAGE_ELEMS) + aoff;
        const uint32_t bbase = smem_u32(smem + (TG_STAGES + s) * TG_STAGE_ELEMS) + boff;

        uint32_t af[2][2][4];
        uint32_t bf[2][4][4];

        ldsm4(af[0][0][0], af[0][0][1], af[0][0][2], af[0][0][3], abase);
        ldsm4(af[0][1][0], af[0][1][1], af[0][1][2], af[0][1][3], abase + 16 * TG_ROWB);
#pragma unroll
        for (int ntp = 0; ntp < 4; ntp++)
            ldsm4(bf[0][ntp][0], bf[0][ntp][1], bf[0][ntp][2], bf[0][ntp][3],
                  bbase + ntp * 16 * TG_ROWB);

#pragma unroll
        for (int ks = 0; ks < 4; ks++) {
            const int cur = ks & 1;
            const int nxt = cur ^ 1;
            if (ks < 3) {
                const uint32_t k2 = (ks + 1) * 32;
                ldsm4(af[nxt][0][0], af[nxt][0][1], af[nxt][0][2], af[nxt][0][3], abase + k2);
                ldsm4(af[nxt][1][0], af[nxt][1][1], af[nxt][1][2], af[nxt][1][3],
                      abase + 16 * TG_ROWB + k2);
#pragma unroll
                for (int ntp = 0; ntp < 4; ntp++)
                    ldsm4(bf[nxt][ntp][0], bf[nxt][ntp][1], bf[nxt][ntp][2], bf[nxt][ntp][3],
                          bbase + ntp * 16 * TG_ROWB + k2);
            }
#pragma unroll
            for (int ntp = 0; ntp < 4; ntp++) {
                mma16816(acc[0][2 * ntp],     af[cur][0], bf[cur][ntp]);
                mma16816(acc[1][2 * ntp],     af[cur][1], bf[cur][ntp]);
                mma16816(acc[0][2 * ntp + 1], af[cur][0], bf[cur][ntp] + 2);
                mma16816(acc[1][2 * ntp + 1], af[cur][1], bf[cur][ntp] + 2);
            }
        }
        __syncthreads();
        if (c + 3 < C) load_chunk(c + 3, s);
        else cp_commit();
    }

    // epilogue
#pragma unroll
    for (int mt = 0; mt < 2; mt++) {
        int row0 = bm + wm * 32 + mt * 16 + g;
        int row1 = row0 + 8;
#pragma unroll
        for (int nt = 0; nt < 8; nt++) {
            int col = bn + wn * 64 + nt * 8 + 2 * t;
            float2 bv = __ldg((const float2*)(bias + col));
            float v0 = acc[mt][nt][0] + bv.x;
            float v1 = acc[mt][nt][1] + bv.y;
            float v2 = acc[mt][nt][2] + bv.x;
            float v3 = acc[mt][nt][3] + bv.y;
            if (RELU) {
                v0 = fmaxf(v0, 0.f); v1 = fmaxf(v1, 0.f);
                v2 = fmaxf(v2, 0.f); v3 = fmaxf(v3, 0.f);
            }
            if (WF32) {
                *(float2*)(Cf32 + (size_t)row0 * Ntot + col) = make_float2(v0, v1);
                *(float2*)(Cf32 + (size_t)row1 * Ntot + col) = make_float2(v2, v3);
            }
            if (WH16) {
                *(uint32_t*)(Ch + (size_t)row0 * Ntot + col) = pack_h2(v0, v1);
                *(uint32_t*)(Ch + (size_t)row1 * Ntot + col) = pack_h2(v2, v3);
            }
        }
    }
}

// ---------------- FFMA2 SGEMM (final N=69 GEMM, fp32) ----------------
__device__ __forceinline__ ull pack2(float lo, float hi) {
    ull r; asm("mov.b64 %0, {%1, %2};" : "=l"(r) : "f"(lo), "f"(hi)); return r;
}
__device__ __forceinline__ void unpack2(ull v, float& lo, float& hi) {
    asm("mov.b64 {%0, %1}, %2;" : "=f"(lo), "=f"(hi) : "l"(v));
}
__device__ __forceinline__ void fma2(ull& d, ull a, ull b) {
    asm("fma.rn.f32x2 %0, %1, %2, %3;" : "=l"(d) : "l"(a), "l"(b), "l"(d));
}

template<bool RELU>
__global__ __launch_bounds__(256)
void sgemm_kernel(const float* __restrict__ A, const float* __restrict__ B,
                  const float* __restrict__ bias, float* __restrict__ C,
                  int M, int Kd, int Nd) {
    __shared__ float As[8][132];
    __shared__ float Bs[8][128];

    const int bm = blockIdx.y * 128;
    const int bn = blockIdx.x * 128;
    const int tid = threadIdx.x;
    const int arow = tid >> 1;
    const int acol = (tid & 1) * 4;
    const int brow = tid >> 5;
    const int bcol = (tid & 31) * 4;
    const int tx = tid & 15;
    const int ty = tid >> 4;

    ull acc2[4][8];
#pragma unroll
    for (int i = 0; i < 4; i++)
#pragma unroll
        for (int j = 0; j < 8; j++) acc2[i][j] = 0ull;

    const bool full_n = (bn + 128 <= Nd);

    for (int k0 = 0; k0 < Kd; k0 += 8) {
        float4 a4 = *(const float4*)(A + (size_t)(bm + arow) * Kd + k0 + acol);
        As[acol + 0][arow] = a4.x;
        As[acol + 1][arow] = a4.y;
        As[acol + 2][arow] = a4.z;
        As[acol + 3][arow] = a4.w;
        if (full_n) {
            *(float4*)&Bs[brow][bcol] =
                *(const float4*)(B + (size_t)(k0 + brow) * Nd + bn + bcol);
        } else {
#pragma unroll
            for (int c = 0; c < 4; c++) {
                int col = bn + bcol + c;
                Bs[brow][bcol + c] = (col < Nd) ? B[(size_t)(k0 + brow) * Nd + col] : 0.f;
            }
        }
        __syncthreads();
#pragma unroll
        for (int k = 0; k < 8; k++) {
            ulonglong2 av0 = *(const ulonglong2*)&As[k][ty * 8];
            ulonglong2 av1 = *(const ulonglong2*)&As[k][ty * 8 + 4];
            ull a2[4] = {av0.x, av0.y, av1.x, av1.y};
            float4 blo = *(const float4*)&Bs[k][tx * 8];
            float4 bhi = *(const float4*)&Bs[k][tx * 8 + 4];
            ull b2[8];
            b2[0] = pack2(blo.x, blo.x); b2[1] = pack2(blo.y, blo.y);
            b2[2] = pack2(blo.z, blo.z); b2[3] = pack2(blo.w, blo.w);
            b2[4] = pack2(bhi.x, bhi.x); b2[5] = pack2(bhi.y, bhi.y);
            b2[6] = pack2(bhi.z, bhi.z); b2[7] = pack2(bhi.w, bhi.w);
#pragma unroll
            for (int i = 0; i < 4; i++)
#pragma unroll
                for (int j = 0; j < 8; j++)
                    fma2(acc2[i][j], a2[i], b2[j]);
        }
        __syncthreads();
    }
#pragma unroll
    for (int i = 0; i < 4; i++) {
        int row_lo = bm + ty * 8 + 2 * i;
        float* c0 = C + (size_t)row_lo * Nd;
        float* c1 = C + (size_t)(row_lo + 1) * Nd;
#pragma unroll
        for (int j = 0; j < 8; j++) {
            int col = bn + tx * 8 + j;
            if (col < Nd) {
                float lo, hi;
                unpack2(acc2[i][j], lo, hi);
                float bv = bias[col];
                lo += bv; hi += bv;
                if (RELU) { lo = fmaxf(lo, 0.f); hi = fmaxf(hi, 0.f); }
                c0[col] = lo;
                c1[col] = hi;
            }
        }
    }
}

// ---------------- dedup streaming attention: one CTA per (pair, <=4 rows) ----------------
#define ACH 8
#define ASTAGES2 2
// floats: ring 2*8*512 + svf 4*512 + sdot 32 + ssq 8 + sw 32 + sred 4 + sstat 8
#define A_SMEM ((ASTAGES2 * ACH * H + MAXR * H + 32 + 8 + 32 + 4 + 8) * 4)

__global__ __launch_bounds__(256)
void attn_kernel(const float* __restrict__ vf,
                 const float* __restrict__ rel_base,
                 __half* __restrict__ rf) {
    extern __shared__ float sm[];
    float* ring  = sm;                               // 2*8*512
    float* svf   = ring + ASTAGES2 * ACH * H;        // 4*512
    float* sdot  = svf + MAXR * H;                   // [8][4]  (chunk-row r, data-row m)
    float* ssq   = sdot + 32;                        // [8]
    float* sw    = ssq + 8;                          // [4][8]  m*8+r
    float* sred  = sw + 32;                          // [4]
    float* sstat = sred + 4;                         // [0..3]=scale_m, [4..7]=s_run_m

    const int u = blockIdx.x;
    if (u >= g_nunits) return;
    const int code = g_units[u];
    const int p = code >> 8;
    const int grp = code & 255;
    const int k = g_hist[p];
    int nr = k - grp * MAXR; if (nr > MAXR) nr = MAXR;
    const int rbase = g_start[p] + grp * MAXR;

    const int tid = threadIdx.x;
    const int lane = tid & 31;
    const int warp = tid >> 5;

    int rows[MAXR];
#pragma unroll
    for (int j = 0; j < MAXR; j++)
        rows[j] = g_perm[rbase + (j < nr ? j : nr - 1)];   // clamp (dup) for safe loads

    const int s = p / CC;
    const int o = p % CC;
    const float* relp = rel_base + (((size_t)s * RR) * CC + o) * H;

    auto load_chunk = [&](int tc) {
        float* dst = ring + (tc & 1) * (ACH * H);
#pragma unroll
        for (int i = 0; i < 4; i++) {
            int idx = tid + i * 256;       // float4 idx 0..1023
            int j = idx >> 7;
            int col4 = idx & 127;
            int r = tc * ACH + j;
            if (r < RR)
                cp_async16(smem_u32(dst + j * H + col4 * 4),
                           relp + (size_t)r * CC * H + col4 * 4);
        }
        cp_commit();
    };

    load_chunk(0);
    load_chunk(1);

    // vf rows -> smem (512 float4 over 256 threads)
#pragma unroll
    for (int i = 0; i < 2; i++) {
        int idx = tid + i * 256;           // 0..511
        int m = idx >> 7;
        int col4 = idx & 127;
        ((float4*)(svf + m * H))[col4] =
            __ldg(&((const float4*)(vf + (size_t)rows[m] * H))[col4]);
    }
    __syncthreads();

    // vf norms: warp m -> sred[m]
    if (warp < MAXR) {
        const float* v = svf + warp * H;
        float part = 0.f;
#pragma unroll
        for (int i = 0; i < 4; i++) {
            float4 x = ((const float4*)v)[lane + 32 * i];
            part += x.x * x.x + x.y * x.y + x.z * x.z + x.w * x.w;
        }
#pragma unroll
        for (int off = 16; off > 0; off >>= 1)
            part += __shfl_xor_sync(0xffffffffu, part, off);
        if (lane == 0) sred[warp] = part;
    }

    const int chunks = (RR + ACH - 1) / ACH;   // 9
    float acc[MAXR][2];
#pragma unroll
    for (int m = 0; m < MAXR; m++) { acc[m][0] = 0.f; acc[m][1] = 0.f; }
    float m_run = -1e30f, s_run = 0.f, vn = 0.f;   // warp-0 softmax state (per lane segment)

    for (int tc = 0; tc < chunks; tc++) {
        CP_WAIT(1);                 // commits at entry = 2 + tc
        __syncthreads();            // chunk tc + (tc==0: sred) visible

        // dots: warp w -> chunk-row w vs all MAXR vfs
        {
            int rglob = tc * ACH + warp;
            if (warp < ACH && rglob < RR) {
                const float4* cb4 = (const float4*)(ring + (tc & 1) * (ACH * H) + warp * H);
                float d0 = 0.f, d1 = 0.f, d2 = 0.f, d3 = 0.f, sq = 0.f;
#pragma unroll
                for (int i = 0; i < 4; i++) {
                    float4 x = cb4[lane + 32 * i];
                    float4 v0 = ((const float4*)(svf + 0 * H))[lane + 32 * i];
                    float4 v1 = ((const float4*)(svf + 1 * H))[lane + 32 * i];
                    float4 v2 = ((const float4*)(svf + 2 * H))[lane + 32 * i];
                    float4 v3 = ((const float4*)(svf + 3 * H))[lane + 32 * i];
                    d0 += x.x * v0.x + x.y * v0.y + x.z * v0.z + x.w * v0.w;
                    d1 += x.x * v1.x + x.y * v1.y + x.z * v1.z + x.w * v1.w;
                    d2 += x.x * v2.x + x.y * v2.y + x.z * v2.z + x.w * v2.w;
                    d3 += x.x * v3.x + x.y * v3.y + x.z * v3.z + x.w * v3.w;
                    sq += x.x * x.x + x.y * x.y + x.z * x.z + x.w * x.w;
                }
#pragma unroll
                for (int off = 16; off > 0; off >>= 1) {
                    d0 += __shfl_down_sync(0xffffffffu, d0, off);
                    d1 += __shfl_down_sync(0xffffffffu, d1, off);
                    d2 += __shfl_down_sync(0xffffffffu, d2, off);
                    d3 += __shfl_down_sync(0xffffffffu, d3, off);
                    sq += __shfl_down_sync(0xffffffffu, sq, off);
                }
                if (lane == 0) {
                    sdot[warp * 4 + 0] = d0;
                    sdot[warp * 4 + 1] = d1;
                    sdot[warp * 4 + 2] = d2;
                    sdot[warp * 4 + 3] = d3;
                    ssq[warp] = sq;
                }
            }
        }
        __syncthreads();

        // warp 0: 4 independent online softmaxes; lane = m*8 + r
        if (warp == 0) {
            const int m = lane >> 3;
            const int r = lane & 7;
            if (tc == 0) vn = sqrtf(sred[m]);
            int rglob = tc * ACH + r;
            float c = (rglob < RR)
                ? sdot[r * 4 + m] / fmaxf(vn * sqrtf(ssq[r]), EPSV)
                : -1e30f;
            float mc = c;
#pragma unroll
            for (int off = 4; off > 0; off >>= 1)
                mc = fmaxf(mc, __shfl_xor_sync(0xffffffffu, mc, off));
            float m_new = fmaxf(m_run, mc);
            float w = __expf(c - m_new);           // invalid rows: exp(-inf)=0
            float wsum = w;
#pragma unroll
            for (int off = 4; off > 0; off >>= 1)
                wsum += __shfl_xor_sync(0xffffffffu, wsum, off);
            float scale = __expf(m_run - m_new);
            s_run = s_run * scale + wsum;
            m_run = m_new;
            sw[lane] = w;                           // sw[m*8+r]
            if (r == 0) sstat[m] = scale;
            if (r == 0 && tc == chunks - 1) sstat[4 + m] = s_run;
        }
        __syncthreads();

        // accumulate (all threads, all MAXR rows)
        {
            float sc0 = sstat[0], sc1 = sstat[1], sc2 = sstat[2], sc3 = sstat[3];
            acc[0][0] *= sc0; acc[0][1] *= sc0;
            acc[1][0] *= sc1; acc[1][1] *= sc1;
            acc[2][0] *= sc2; acc[2][1] *= sc2;
            acc[3][0] *= sc3; acc[3][1] *= sc3;
            const float* cb = ring + (tc & 1) * (ACH * H);
#pragma unroll
            for (int r = 0; r < ACH; r++) {
                float v0 = cb[r * H + tid];
                float v1 = cb[r * H + tid + 256];
#pragma unroll
                for (int m = 0; m < MAXR; m++) {
                    float wr = sw[m * 8 + r];
                    acc[m][0] = fmaf(wr, v0, acc[m][0]);
                    acc[m][1] = fmaf(wr, v1, acc[m][1]);
                }
            }
        }
        __syncthreads();            // buffer reusable

        if (tc + 2 < chunks) load_chunk(tc + 2);
        else cp_commit();
    }

    // write outputs for real rows
    for (int m = 0; m < nr; m++) {
        float inv = 1.f / sstat[4 + m];
        size_t base = (size_t)rows[m] * 2 * H;
        rf[base + tid]           = __float2half_rn(svf[m * H + tid]);
        rf[base + tid + 256]     = __float2half_rn(svf[m * H + tid + 256]);
        rf[base + H + tid]       = __float2half_rn(acc[m][0] * inv);
        rf[base + H + tid + 256] = __float2half_rn(acc[m][1] * inv);
    }
}

// ---------------- launch ----------------
extern "C" void kernel_launch(void* const* d_in, const int* in_sizes, int n_in,
                              void* d_out, int out_size) {
    if (n_in < 14) return;
    const float* sfeat = (const float*)d_in[0];
    const float* pfeat = (const float*)d_in[1];
    const float* ofeat = (const float*)d_in[2];
    const float* rel   = (const float*)d_in[3];
    const float* w1    = (const float*)d_in[4];
    const float* b1    = (const float*)d_in[5];
    const float* w2    = (const float*)d_in[6];
    const float* b2    = (const float*)d_in[7];
    const float* rw1   = (const float*)d_in[8];
    const float* rb1   = (const float*)d_in[9];
    const float* rw2   = (const float*)d_in[10];
    const float* rb2   = (const float*)d_in[11];
    const int*   scats = (const int*)d_in[12];
    const int*   ocats = (const int*)d_in[13];
    float* out = (float*)d_out;

    __half *p_vcat, *p_h, *p_rf, *p_w1t, *p_w2t, *p_rw1t;
    float *p_vf, *p_h2;
    void *p_hist, *p_nunits;
    cudaGetSymbolAddress((void**)&p_vcat, g_vcat);
    cudaGetSymbolAddress((void**)&p_h, g_h);
    cudaGetSymbolAddress((void**)&p_vf, g_vf);
    cudaGetSymbolAddress((void**)&p_rf, g_rf);
    cudaGetSymbolAddress((void**)&p_h2, g_h2);
    cudaGetSymbolAddress((void**)&p_w1t, g_w1t);
    cudaGetSymbolAddress((void**)&p_w2t, g_w2t);
    cudaGetSymbolAddress((void**)&p_rw1t, g_rw1t);
    cudaGetSymbolAddress(&p_hist, g_hist);
    cudaGetSymbolAddress(&p_nunits, g_nunits);

    const int thr = 256;

    // dedup structures
    cudaMemsetAsync(p_hist, 0, NPAIRS * sizeof(int));
    cudaMemsetAsync(p_nunits, 0, sizeof(int));
    pair_hist_kernel<<<(NROWS + thr - 1) / thr, thr>>>(scats, ocats);
    pair_scan_kernel<<<1, 1024>>>();
    pair_scatter_kernel<<<(NROWS + thr - 1) / thr, thr>>>(scats, ocats);
    pair_units_kernel<<<(NPAIRS + thr - 1) / thr, thr>>>();

    // 0) weight transpose -> fp16
    wtrans_kernel<<<(int)(((size_t)3 * H * H + thr - 1) / thr), thr>>>(w1, p_w1t, 3 * H, H);
    wtrans_kernel<<<(int)(((size_t)H * H + thr - 1) / thr), thr>>>(w2, p_w2t, H, H);
    wtrans_kernel<<<(int)(((size_t)2 * H * H + thr - 1) / thr), thr>>>(rw1, p_rw1t, 2 * H, H);

    // 1) concat -> fp16
    {
        size_t total4 = (size_t)NROWS * 3 * H / 4;
        concat_kernel<<<(int)((total4 + thr - 1) / thr), thr>>>(sfeat, pfeat, ofeat);
    }
    // 2) h = relu(vcat @ w1 + b1) -> fp16
    {
        cudaFuncSetAttribute(tgemm_kernel<true, false, true>,
                             cudaFuncAttributeMaxDynamicSharedMemorySize, TG_SMEM);
        dim3 grid(H / 128, NROWS / 128);
        tgemm_kernel<true, false, true><<<grid, 256, TG_SMEM>>>(
            p_vcat, p_w1t, b1, p_h, nullptr, 3 * H, H);
    }
    // 3) vf = relu(h @ w2 + b2) -> f32
    {
        cudaFuncSetAttribute(tgemm_kernel<false, true, true>,
                             cudaFuncAttributeMaxDynamicSharedMemorySize, TG_SMEM);
        dim3 grid(H / 128, NROWS / 128);
        tgemm_kernel<false, true, true><<<grid, 256, TG_SMEM>>>(
            p_h, p_w2t, b2, nullptr, p_vf, H, H);
    }
    // 4) dedup streaming attention -> rf fp16
    {
        cudaFuncSetAttribute(attn_kernel, cudaFuncAttributeMaxDynamicSharedMemorySize, A_SMEM);
        attn_kernel<<<NROWS, 256, A_SMEM>>>(p_vf, rel, p_rf);
    }
    // 5) h2 = relu(rf @ rw1 + rb1) -> f32
    {
        dim3 grid(H / 128, NROWS / 128);
        tgemm_kernel<false, true, true><<<grid, 256, TG_SMEM>>>(
            p_rf, p_rw1t, rb1, nullptr, p_h2, 2 * H, H);
    }
    // 6) plogits = h2 @ rw2 + rb2   (FFMA2 fp32, Nd=69)
    {
        dim3 grid(1, NROWS / 128);
        sgemm_kernel<false><<<grid, 256>>>(p_h2, rw2, rb2, out, NROWS, H, PP);
    }
}